// round 13
// baseline (speedup 1.0000x reference)
#include <cuda_runtime.h>
#include <cuda.h>
#include <cuda_fp16.h>
#include <cstdint>

// ---------------- problem constants ----------------
#define K_DIM 4096
#define N_DIM 4096
#define M_DIM 8192            // 4 * 2048
#define GROUPS 32
#define PACKED_PER_ROW 2048   // K/2

// ---------------- GEMM tiling ----------------
#define BM 128
#define BN 128
#define BK 64                 // halves per K-chunk (=128B rows, SW128 atom)
#define NCHUNK (K_DIM / BK)   // 64

// fp16 scratch (static __device__ — no runtime allocation)
__device__ __half g_Wh[(size_t)N_DIM * K_DIM];   // 32 MB
__device__ __half g_Xh[(size_t)M_DIM * K_DIM];   // 64 MB

// ---------------- PTX helpers (baseline sm_90 features only) ----------------
__device__ __forceinline__ uint32_t smem_u32(const void* p) {
    uint32_t a;
    asm("{ .reg .u64 t; cvta.to.shared.u64 t, %1; cvt.u32.u64 %0, t; }" : "=r"(a) : "l"(p));
    return a;
}

#define CP_ASYNC16(dst, src) \
    asm volatile("cp.async.cg.shared.global [%0], [%1], 16;\n" :: "r"(dst), "l"(src))
#define CP_COMMIT()  asm volatile("cp.async.commit_group;\n" ::: "memory")
#define CP_WAIT(n)   asm volatile("cp.async.wait_group %0;\n" :: "n"(n) : "memory")

__device__ __forceinline__ void ldsm_x4(uint32_t& r0, uint32_t& r1,
                                        uint32_t& r2, uint32_t& r3, uint32_t addr) {
    asm volatile("ldmatrix.sync.aligned.m8n8.x4.shared.b16 {%0,%1,%2,%3}, [%4];"
                 : "=r"(r0), "=r"(r1), "=r"(r2), "=r"(r3) : "r"(addr));
}

__device__ __forceinline__ void mma_16816(float* d, const uint32_t* a,
                                          const uint32_t* b) {
    asm volatile(
        "mma.sync.aligned.m16n8k16.row.col.f32.f16.f16.f32 "
        "{%0,%1,%2,%3}, {%4,%5,%6,%7}, {%8,%9}, {%0,%1,%2,%3};"
        : "+f"(d[0]), "+f"(d[1]), "+f"(d[2]), "+f"(d[3])
        : "r"(a[0]), "r"(a[1]), "r"(a[2]), "r"(a[3]), "r"(b[0]), "r"(b[1]));
}

#define MBARRIER_INIT(addr, cnt) \
    asm volatile("mbarrier.init.shared.b64 [%0], %1;" :: "r"(addr), "r"(cnt) : "memory")
#define MBARRIER_EXPECT_TX(addr, bytes) \
    asm volatile("mbarrier.arrive.expect_tx.shared.b64 _, [%0], %1;" \
                 :: "r"(addr), "r"((uint32_t)(bytes)) : "memory")
#define MBARRIER_ARRIVE(addr) \
    asm volatile("mbarrier.arrive.shared.b64 _, [%0];" :: "r"(addr) : "memory")
#define FENCE_ASYNC() asm volatile("fence.proxy.async.shared::cta;" ::: "memory")

#define MBAR_WAIT(addr, parity) do {                                          \
    uint32_t _mb = (addr); uint32_t _ph = (parity); uint32_t _done;           \
    asm volatile("{\n\t.reg .pred p;\n\t"                                     \
        "mbarrier.try_wait.parity.acquire.cta.shared::cta.b64 p, [%1], %2;\n\t"\
        "selp.b32 %0, 1, 0, p;\n\t}" : "=r"(_done) : "r"(_mb), "r"(_ph) : "memory"); \
    if (!_done) {                                                             \
        asm volatile("{\n\t.reg .pred P1;\n\t"                                \
            "WL_%=:\n\t"                                                      \
            "mbarrier.try_wait.parity.acquire.cta.shared::cta.b64 P1, [%0], %1, 0x989680;\n\t" \
            "@P1 bra.uni WD_%=;\n\t"                                          \
            "bra.uni WL_%=;\n\t"                                              \
            "WD_%=:\n\t}" :: "r"(_mb), "r"(_ph) : "memory");                  \
    }                                                                         \
} while (0)

__device__ __forceinline__ void tma2d(uint32_t dst, const CUtensorMap* tm,
                                      int x, int y, uint32_t mbar) {
    asm volatile(
        "cp.async.bulk.tensor.2d.shared::cta.global.tile.mbarrier::complete_tx::bytes "
        "[%0], [%1, {%2, %3}], [%4];"
        :: "r"(dst), "l"(tm), "r"(x), "r"(y), "r"(mbar) : "memory");
}

// ---------------- TMA GEMM smem layout ----------------
#define TSTG 32768                          // A 16KB + B 16KB, SW128
#define TMA_NSTAGE 3
#define TMA_SM_BAR 0                        // 3 full + 3 empty mbarriers (48B)
#define TMA_SM_TILE 1024
#define TMA_SM_TOTAL (TMA_SM_TILE + TMA_NSTAGE * TSTG)   // 99328 -> 2 CTAs/SM

// ---------------- fallback (cp.async) layout — R4 proven ----------------
#define LDS_ROW 72
#define ASTG (BM * LDS_ROW * 2)            // 18432 B
#define FSTG (2 * ASTG)                    // 36864 B
#define FB_SM_TOTAL (2 * FSTG)             // 73728 B -> 2 CTAs/SM

// ---------------------------------------------------------------------------
// Merged prep kernel: blocks [0, DQ_BLOCKS) dequantize W; rest convert X.
// ---------------------------------------------------------------------------
#define DQ_ITEMS ((N_DIM * PACKED_PER_ROW) / 4)
#define CV_ITEMS ((M_DIM * K_DIM) / 8)
#define DQ_BLOCKS (DQ_ITEMS / 256)
#define CV_BLOCKS (CV_ITEMS / 256)

__global__ void prep_kernel(const int* __restrict__ wp,
                            const float* __restrict__ scales,
                            const float* __restrict__ x) {
    if (blockIdx.x < DQ_BLOCKS) {
        int idx = blockIdx.x * 256 + threadIdx.x;
        int4 p = reinterpret_cast<const int4*>(wp)[idx];
        int j4 = idx << 2;
        int o = j4 >> 11;
        int j = j4 & 2047;
        float s = scales[o * GROUPS + (j >> 6)];
        uint4 v;
        {
            __half2 h = __halves2half2(__float2half_rn((float)((p.x & 15) - 8) * s),
                                       __float2half_rn((float)(((p.x >> 4) & 15) - 8) * s));
            v.x = *reinterpret_cast<uint32_t*>(&h);
        }
        {
            __half2 h = __halves2half2(__float2half_rn((float)((p.y & 15) - 8) * s),
                                       __float2half_rn((float)(((p.y >> 4) & 15) - 8) * s));
            v.y = *reinterpret_cast<uint32_t*>(&h);
        }
        {
            __half2 h = __halves2half2(__float2half_rn((float)((p.z & 15) - 8) * s),
                                       __float2half_rn((float)(((p.z >> 4) & 15) - 8) * s));
            v.z = *reinterpret_cast<uint32_t*>(&h);
        }
        {
            __half2 h = __halves2half2(__float2half_rn((float)((p.w & 15) - 8) * s),
                                       __float2half_rn((float)(((p.w >> 4) & 15) - 8) * s));
            v.w = *reinterpret_cast<uint32_t*>(&h);
        }
        reinterpret_cast<uint4*>(g_Wh)[idx] = v;
    } else {
        int idx = (blockIdx.x - DQ_BLOCKS) * 256 + threadIdx.x;
        float4 v0 = reinterpret_cast<const float4*>(x)[2 * idx];
        float4 v1 = reinterpret_cast<const float4*>(x)[2 * idx + 1];
        __half2 a = __floats2half2_rn(v0.x, v0.y);
        __half2 b = __floats2half2_rn(v0.z, v0.w);
        __half2 c = __floats2half2_rn(v1.x, v1.y);
        __half2 d = __floats2half2_rn(v1.z, v1.w);
        uint4 u;
        u.x = *reinterpret_cast<uint32_t*>(&a);
        u.y = *reinterpret_cast<uint32_t*>(&b);
        u.z = *reinterpret_cast<uint32_t*>(&c);
        u.w = *reinterpret_cast<uint32_t*>(&d);
        reinterpret_cast<uint4*>(g_Xh)[idx] = u;
    }
}

// ---------------------------------------------------------------------------
// TMA HMMA GEMM: 128x128 tile, BK=64, SW128 tiles, 3-stage producer/consumer
// mbarrier pipeline + intra-chunk fragment double-buffering (software
// pipeline): LDSMs of k-step s+1 issue before the HMMAs of k-step s.
// ---------------------------------------------------------------------------
__global__ void __launch_bounds__(256, 2)
gemm_tma(const __grid_constant__ CUtensorMap tmA,
         const __grid_constant__ CUtensorMap tmB,
         const float* __restrict__ bias, float* __restrict__ out) {
    extern __shared__ __align__(1024) char smem[];
    const uint32_t sb = smem_u32(smem);
    const uint32_t sfull  = sb + TMA_SM_BAR;        // 3 x 8B
    const uint32_t sempty = sb + TMA_SM_BAR + 24;   // 3 x 8B
    const uint32_t stile  = sb + TMA_SM_TILE;
    const int tid  = threadIdx.x;
    const int lane = tid & 31;
    const int wid  = tid >> 5;
    const int wm0 = (wid >> 2) * 64;        // warp_m 0..1
    const int wn0 = (wid & 3) * 32;         // warp_n 0..3
    const int bm = blockIdx.y * BM;
    const int bn = blockIdx.x * BN;

    if (tid == 0) {
        MBARRIER_INIT(sfull + 0, 1);
        MBARRIER_INIT(sfull + 8, 1);
        MBARRIER_INIT(sfull + 16, 1);
        MBARRIER_INIT(sempty + 0, 8);       // one arrive per warp
        MBARRIER_INIT(sempty + 8, 8);
        MBARRIER_INIT(sempty + 16, 8);
        FENCE_ASYNC();
    }
    __syncthreads();                         // barriers visible (only CTA sync)

    auto issue = [&](int c) {
        int s = c % TMA_NSTAGE;
        uint32_t mb = sfull + s * 8;
        uint32_t ab = stile + s * TSTG;
        MBARRIER_EXPECT_TX(mb, 2 * 16384);
        tma2d(ab,          &tmA, c * BK, bm, mb);
        tma2d(ab + 16384,  &tmB, c * BK, bn, mb);
    };

    if (tid == 0) { issue(0); issue(1); }

    // swizzled ldmatrix address components:
    // addr = tile + row*128 + ((ks*32 + seg16) ^ ((row&7)*16))
    uint32_t arow[4], arx[4], brow[2], brx[2];
    #pragma unroll
    for (int mi = 0; mi < 4; mi++) {
        int r = wm0 + mi * 16 + (lane & 15);
        arow[mi] = r * 128;
        arx[mi]  = (r & 7) * 16;
    }
    #pragma unroll
    for (int p = 0; p < 2; p++) {
        int r = wn0 + p * 16 + (lane & 15);
        brow[p] = r * 128;
        brx[p]  = (r & 7) * 16;
    }
    const uint32_t seg16 = (lane >> 4) * 16;

    float acc[4][4][4];
    #pragma unroll
    for (int i = 0; i < 4; i++)
        #pragma unroll
        for (int j = 0; j < 4; j++)
            #pragma unroll
            for (int q = 0; q < 4; q++)
                acc[i][j][q] = 0.0f;

    // two fragment sets for intra-chunk software pipelining
    uint32_t fa[2][4][4], fb[2][4][2];

    auto load_frags = [&](uint32_t abase, uint32_t bbase, int ks, int buf) {
        uint32_t kb = ks * 32 + seg16;
        #pragma unroll
        for (int mi = 0; mi < 4; mi++)
            ldsm_x4(fa[buf][mi][0], fa[buf][mi][1], fa[buf][mi][2], fa[buf][mi][3],
                    abase + arow[mi] + (kb ^ arx[mi]));
        #pragma unroll
        for (int p = 0; p < 2; p++) {
            uint32_t r0, r1, r2, r3;
            ldsm_x4(r0, r1, r2, r3, bbase + brow[p] + (kb ^ brx[p]));
            fb[buf][p * 2 + 0][0] = r0; fb[buf][p * 2 + 0][1] = r2;
            fb[buf][p * 2 + 1][0] = r1; fb[buf][p * 2 + 1][1] = r3;
        }
    };

    auto do_mma = [&](int buf) {
        #pragma unroll
        for (int mi = 0; mi < 4; mi++)
            #pragma unroll
            for (int nj = 0; nj < 4; nj++)
                mma_16816(acc[mi][nj], fa[buf][mi], fb[buf][nj]);
    };

    for (int c = 0; c < NCHUNK; c++) {
        int s = c % TMA_NSTAGE;
        MBAR_WAIT(sfull + s * 8, (c / TMA_NSTAGE) & 1);   // data resident

        uint32_t abase = stile + s * TSTG;
        uint32_t bbase = abase + 16384;

        // software pipeline: LDSMs of ks+1 issue before HMMAs of ks
        load_frags(abase, bbase, 0, 0);
        load_frags(abase, bbase, 1, 1);
        do_mma(0);                           // ks0
        load_frags(abase, bbase, 2, 0);
        do_mma(1);                           // ks1
        load_frags(abase, bbase, 3, 1);
        do_mma(0);                           // ks2
        do_mma(1);                           // ks3

        // this warp is done reading stage s
        if (lane == 0) MBARRIER_ARRIVE(sempty + s * 8);

        // producer: issue chunk c+2 once its stage's previous occupant (c-1)
        // has been consumed by all 8 warps
        if (tid == 0 && c + 2 < NCHUNK) {
            int cn = c + 2;
            int sn = cn % TMA_NSTAGE;
            if (cn >= TMA_NSTAGE)
                MBAR_WAIT(sempty + sn * 8, ((cn - TMA_NSTAGE) / TMA_NSTAGE) & 1);
            issue(cn);
        }
    }

    // ---- epilogue (per-warp; no sync needed, each warp owns its outputs) ----
    const int row0 = lane >> 2;
    const int col0 = (lane & 3) * 2;
    #pragma unroll
    for (int mi = 0; mi < 4; mi++) {
        int m = bm + wm0 + mi * 16 + row0;
        #pragma unroll
        for (int nj = 0; nj < 4; nj++) {
            int n = bn + wn0 + nj * 8 + col0;
            float b0 = __ldg(&bias[n]);
            float b1 = __ldg(&bias[n + 1]);
            float2 v0 = make_float2(acc[mi][nj][0] + b0, acc[mi][nj][1] + b1);
            float2 v1 = make_float2(acc[mi][nj][2] + b0, acc[mi][nj][3] + b1);
            *reinterpret_cast<float2*>(&out[(size_t)m * N_DIM + n]) = v0;
            *reinterpret_cast<float2*>(&out[(size_t)(m + 8) * N_DIM + n]) = v1;
        }
    }
}

// ---------------------------------------------------------------------------
// Fallback HMMA GEMM (R4 exact: cp.async, 2-stage, 873us proven)
// ---------------------------------------------------------------------------
__global__ void __launch_bounds__(256, 2)
gemm_hmma(const float* __restrict__ bias, float* __restrict__ out) {
    extern __shared__ char smem[];
    const uint32_t sb = smem_u32(smem);
    const int tid  = threadIdx.x;
    const int lane = tid & 31;
    const int wid  = tid >> 5;
    const int wm0 = (wid >> 2) * 64;
    const int wn0 = (wid & 3) * 32;
    const int bm = blockIdx.y * BM;
    const int bn = blockIdx.x * BN;

    const char* Xbase = (const char*)(g_Xh + (size_t)bm * K_DIM);
    const char* Wbase = (const char*)(g_Wh + (size_t)bn * K_DIM);
    const int ld_row = tid >> 3;
    const int ld_seg = tid & 7;

    auto load_chunk = [&](int c, int s) {
        uint32_t abase = sb + s * FSTG;
        uint32_t bbase = abase + ASTG;
        const char* asrc = Xbase + c * (BK * 2);
        const char* bsrc = Wbase + c * (BK * 2);
        #pragma unroll
        for (int t = 0; t < 4; t++) {
            int row = ld_row + t * 32;
            uint32_t doff = row * (LDS_ROW * 2) + ld_seg * 16;
            size_t   soff = (size_t)row * (K_DIM * 2) + ld_seg * 16;
            CP_ASYNC16(abase + doff, asrc + soff);
            CP_ASYNC16(bbase + doff, bsrc + soff);
        }
        CP_COMMIT();
    };

    uint32_t aoff[4], boff[2];
    #pragma unroll
    for (int mi = 0; mi < 4; mi++)
        aoff[mi] = (wm0 + mi * 16 + (lane & 15)) * (LDS_ROW * 2) + ((lane >> 4) << 4);
    #pragma unroll
    for (int nj = 0; nj < 2; nj++)
        boff[nj] = (wn0 + nj * 16 + (lane & 15)) * (LDS_ROW * 2) + ((lane >> 4) << 4);

    float acc[4][4][4];
    #pragma unroll
    for (int i = 0; i < 4; i++)
        #pragma unroll
        for (int j = 0; j < 4; j++)
            #pragma unroll
            for (int q = 0; q < 4; q++)
                acc[i][j][q] = 0.0f;

    load_chunk(0, 0);
    for (int c = 0; c < NCHUNK; c++) {
        CP_WAIT(0);
        __syncthreads();
        if (c + 1 < NCHUNK)
            load_chunk(c + 1, (c + 1) & 1);
        uint32_t abase = sb + (c & 1) * FSTG;
        uint32_t bbase = abase + ASTG;
        #pragma unroll
        for (int ks = 0; ks < 4; ks++) {
            uint32_t koff = ks * 32;
            uint32_t a[4][4], b[4][2];
            #pragma unroll
            for (int mi = 0; mi < 4; mi++)
                ldsm_x4(a[mi][0], a[mi][1], a[mi][2], a[mi][3], abase + aoff[mi] + koff);
            #pragma unroll
            for (int njp = 0; njp < 2; njp++) {
                uint32_t r0, r1, r2, r3;
                ldsm_x4(r0, r1, r2, r3, bbase + boff[njp] + koff);
                b[njp * 2 + 0][0] = r0; b[njp * 2 + 0][1] = r2;
                b[njp * 2 + 1][0] = r1; b[njp * 2 + 1][1] = r3;
            }
            #pragma unroll
            for (int mi = 0; mi < 4; mi++)
                #pragma unroll
                for (int nj = 0; nj < 4; nj++)
                    mma_16816(acc[mi][nj], a[mi], b[nj]);
        }
    }
    const int row0 = lane >> 2;
    const int col0 = (lane & 3) * 2;
    #pragma unroll
    for (int mi = 0; mi < 4; mi++) {
        int m = bm + wm0 + mi * 16 + row0;
        #pragma unroll
        for (int nj = 0; nj < 4; nj++) {
            int n = bn + wn0 + nj * 8 + col0;
            float b0 = __ldg(&bias[n]);
            float b1 = __ldg(&bias[n + 1]);
            float2 v0 = make_float2(acc[mi][nj][0] + b0, acc[mi][nj][1] + b1);
            float2 v1 = make_float2(acc[mi][nj][2] + b0, acc[mi][nj][3] + b1);
            *reinterpret_cast<float2*>(&out[(size_t)m * N_DIM + n]) = v0;
            *reinterpret_cast<float2*>(&out[(size_t)(m + 8) * N_DIM + n]) = v1;
        }
    }
}

// ---------------------------------------------------------------------------
// Launch
// inputs: 0=x f32, 1=weight_packed i32, 2=scales f32, 3=zeros, 4=bias f32
// ---------------------------------------------------------------------------
typedef CUresult (*EncodeFn)(CUtensorMap*, CUtensorMapDataType, cuuint32_t,
                             void*, const cuuint64_t*, const cuuint64_t*,
                             const cuuint32_t*, const cuuint32_t*,
                             CUtensorMapInterleave, CUtensorMapSwizzle,
                             CUtensorMapL2promotion, CUtensorMapFloatOOBfill);

extern "C" void kernel_launch(void* const* d_in, const int* in_sizes, int n_in,
                              void* d_out, int out_size) {
    const float* x      = (const float*)d_in[0];
    const int*   wp     = (const int*)d_in[1];
    const float* scales = (const float*)d_in[2];
    const float* bias   = (const float*)d_in[4];
    float*       out    = (float*)d_out;
    (void)in_sizes; (void)n_in; (void)out_size;

    static int mode = -1;
    static CUtensorMap tmA, tmB;
    if (mode < 0) {
        mode = 0;
        EncodeFn enc = nullptr;
        cudaDriverEntryPointQueryResult qr;
        if (cudaGetDriverEntryPoint("cuTensorMapEncodeTiled", (void**)&enc,
                                    cudaEnableDefault, &qr) == cudaSuccess &&
            enc != nullptr) {
            void *pX = nullptr, *pW = nullptr;
            cudaGetSymbolAddress(&pX, g_Xh);
            cudaGetSymbolAddress(&pW, g_Wh);
            cuuint64_t dimsA[2] = {K_DIM, M_DIM};
            cuuint64_t dimsB[2] = {K_DIM, N_DIM};
            cuuint64_t strides[1] = {K_DIM * 2};
            cuuint32_t box[2] = {BK, BM};
            cuuint32_t es[2] = {1, 1};
            CUresult r1 = enc(&tmA, CU_TENSOR_MAP_DATA_TYPE_UINT16, 2, pX,
                              dimsA, strides, box, es,
                              CU_TENSOR_MAP_INTERLEAVE_NONE,
                              CU_TENSOR_MAP_SWIZZLE_128B,
                              CU_TENSOR_MAP_L2_PROMOTION_L2_128B,
                              CU_TENSOR_MAP_FLOAT_OOB_FILL_NONE);
            CUresult r2 = enc(&tmB, CU_TENSOR_MAP_DATA_TYPE_UINT16, 2, pW,
                              dimsB, strides, box, es,
                              CU_TENSOR_MAP_INTERLEAVE_NONE,
                              CU_TENSOR_MAP_SWIZZLE_128B,
                              CU_TENSOR_MAP_L2_PROMOTION_L2_128B,
                              CU_TENSOR_MAP_FLOAT_OOB_FILL_NONE);
            if (r1 == CUDA_SUCCESS && r2 == CUDA_SUCCESS) mode = 1;
        }
        cudaFuncSetAttribute(gemm_tma,
                             cudaFuncAttributeMaxDynamicSharedMemorySize,
                             TMA_SM_TOTAL);
        cudaFuncSetAttribute(gemm_hmma,
                             cudaFuncAttributeMaxDynamicSharedMemorySize,
                             FB_SM_TOTAL);
    }

    prep_kernel<<<DQ_BLOCKS + CV_BLOCKS, 256>>>(wp, scales, x);

    dim3 grid(N_DIM / BN, M_DIM / BM);   // (32, 64)
    if (mode == 1) {
        gemm_tma<<<grid, 256, TMA_SM_TOTAL>>>(tmA, tmB, bias, out);
    } else {
        gemm_hmma<<<grid, 256, FB_SM_TOTAL>>>(bias, out);
    }
}

// round 14
// speedup vs baseline: 1.5675x; 1.5675x over previous
#include <cuda_runtime.h>
#include <cuda.h>
#include <cuda_fp16.h>
#include <cstdint>

// ---------------- problem constants ----------------
#define K_DIM 4096
#define N_DIM 4096
#define M_DIM 8192            // 4 * 2048
#define GROUPS 32
#define PACKED_PER_ROW 2048   // K/2

// ---------------- GEMM tiling ----------------
#define BM 128
#define BN 128
#define BK 64                 // halves per K-chunk (=128B rows, SW128 atom)
#define NCHUNK (K_DIM / BK)   // 64
#define NTHREADS 288          // 8 compute warps + 1 producer warp

// fp16 scratch (static __device__ — no runtime allocation)
__device__ __half g_Wh[(size_t)N_DIM * K_DIM];   // 32 MB
__device__ __half g_Xh[(size_t)M_DIM * K_DIM];   // 64 MB

// ---------------- PTX helpers (baseline sm_90 features only) ----------------
__device__ __forceinline__ uint32_t smem_u32(const void* p) {
    uint32_t a;
    asm("{ .reg .u64 t; cvta.to.shared.u64 t, %1; cvt.u32.u64 %0, t; }" : "=r"(a) : "l"(p));
    return a;
}

#define CP_ASYNC16(dst, src) \
    asm volatile("cp.async.cg.shared.global [%0], [%1], 16;\n" :: "r"(dst), "l"(src))
#define CP_COMMIT()  asm volatile("cp.async.commit_group;\n" ::: "memory")
#define CP_WAIT(n)   asm volatile("cp.async.wait_group %0;\n" :: "n"(n) : "memory")

__device__ __forceinline__ void ldsm_x4(uint32_t& r0, uint32_t& r1,
                                        uint32_t& r2, uint32_t& r3, uint32_t addr) {
    asm volatile("ldmatrix.sync.aligned.m8n8.x4.shared.b16 {%0,%1,%2,%3}, [%4];"
                 : "=r"(r0), "=r"(r1), "=r"(r2), "=r"(r3) : "r"(addr));
}

__device__ __forceinline__ void mma_16816(float* d, const uint32_t* a,
                                          const uint32_t* b) {
    asm volatile(
        "mma.sync.aligned.m16n8k16.row.col.f32.f16.f16.f32 "
        "{%0,%1,%2,%3}, {%4,%5,%6,%7}, {%8,%9}, {%0,%1,%2,%3};"
        : "+f"(d[0]), "+f"(d[1]), "+f"(d[2]), "+f"(d[3])
        : "r"(a[0]), "r"(a[1]), "r"(a[2]), "r"(a[3]), "r"(b[0]), "r"(b[1]));
}

#define MBARRIER_INIT(addr, cnt) \
    asm volatile("mbarrier.init.shared.b64 [%0], %1;" :: "r"(addr), "r"(cnt) : "memory")
#define MBARRIER_EXPECT_TX(addr, bytes) \
    asm volatile("mbarrier.arrive.expect_tx.shared.b64 _, [%0], %1;" \
                 :: "r"(addr), "r"((uint32_t)(bytes)) : "memory")
#define MBARRIER_ARRIVE(addr) \
    asm volatile("mbarrier.arrive.shared.b64 _, [%0];" :: "r"(addr) : "memory")
#define FENCE_ASYNC() asm volatile("fence.proxy.async.shared::cta;" ::: "memory")

#define MBAR_WAIT(addr, parity) do {                                          \
    uint32_t _mb = (addr); uint32_t _ph = (parity); uint32_t _done;           \
    asm volatile("{\n\t.reg .pred p;\n\t"                                     \
        "mbarrier.try_wait.parity.acquire.cta.shared::cta.b64 p, [%1], %2;\n\t"\
        "selp.b32 %0, 1, 0, p;\n\t}" : "=r"(_done) : "r"(_mb), "r"(_ph) : "memory"); \
    if (!_done) {                                                             \
        asm volatile("{\n\t.reg .pred P1;\n\t"                                \
            "WL_%=:\n\t"                                                      \
            "mbarrier.try_wait.parity.acquire.cta.shared::cta.b64 P1, [%0], %1, 0x989680;\n\t" \
            "@P1 bra.uni WD_%=;\n\t"                                          \
            "bra.uni WL_%=;\n\t"                                              \
            "WD_%=:\n\t}" :: "r"(_mb), "r"(_ph) : "memory");                  \
    }                                                                         \
} while (0)

__device__ __forceinline__ void tma2d(uint32_t dst, const CUtensorMap* tm,
                                      int x, int y, uint32_t mbar) {
    asm volatile(
        "cp.async.bulk.tensor.2d.shared::cta.global.tile.mbarrier::complete_tx::bytes "
        "[%0], [%1, {%2, %3}], [%4];"
        :: "r"(dst), "l"(tm), "r"(x), "r"(y), "r"(mbar) : "memory");
}

// ---------------- TMA GEMM smem layout ----------------
#define TSTG 32768                          // A 16KB + B 16KB, SW128
#define TMA_NSTAGE 3
#define TMA_SM_BAR 0                        // 3 full + 3 empty mbarriers (48B)
#define TMA_SM_TILE 1024
#define TMA_SM_TOTAL (TMA_SM_TILE + TMA_NSTAGE * TSTG)   // 99328 -> 2 CTAs/SM

// ---------------- fallback (cp.async) layout — R4 proven ----------------
#define LDS_ROW 72
#define ASTG (BM * LDS_ROW * 2)            // 18432 B
#define FSTG (2 * ASTG)                    // 36864 B
#define FB_SM_TOTAL (2 * FSTG)             // 73728 B -> 2 CTAs/SM

// ---------------------------------------------------------------------------
// Merged prep kernel: blocks [0, DQ_BLOCKS) dequantize W; rest convert X.
// ---------------------------------------------------------------------------
#define DQ_ITEMS ((N_DIM * PACKED_PER_ROW) / 4)
#define CV_ITEMS ((M_DIM * K_DIM) / 8)
#define DQ_BLOCKS (DQ_ITEMS / 256)
#define CV_BLOCKS (CV_ITEMS / 256)

__global__ void prep_kernel(const int* __restrict__ wp,
                            const float* __restrict__ scales,
                            const float* __restrict__ x) {
    if (blockIdx.x < DQ_BLOCKS) {
        int idx = blockIdx.x * 256 + threadIdx.x;
        int4 p = reinterpret_cast<const int4*>(wp)[idx];
        int j4 = idx << 2;
        int o = j4 >> 11;
        int j = j4 & 2047;
        float s = scales[o * GROUPS + (j >> 6)];
        uint4 v;
        {
            __half2 h = __halves2half2(__float2half_rn((float)((p.x & 15) - 8) * s),
                                       __float2half_rn((float)(((p.x >> 4) & 15) - 8) * s));
            v.x = *reinterpret_cast<uint32_t*>(&h);
        }
        {
            __half2 h = __halves2half2(__float2half_rn((float)((p.y & 15) - 8) * s),
                                       __float2half_rn((float)(((p.y >> 4) & 15) - 8) * s));
            v.y = *reinterpret_cast<uint32_t*>(&h);
        }
        {
            __half2 h = __halves2half2(__float2half_rn((float)((p.z & 15) - 8) * s),
                                       __float2half_rn((float)(((p.z >> 4) & 15) - 8) * s));
            v.z = *reinterpret_cast<uint32_t*>(&h);
        }
        {
            __half2 h = __halves2half2(__float2half_rn((float)((p.w & 15) - 8) * s),
                                       __float2half_rn((float)(((p.w >> 4) & 15) - 8) * s));
            v.w = *reinterpret_cast<uint32_t*>(&h);
        }
        reinterpret_cast<uint4*>(g_Wh)[idx] = v;
    } else {
        int idx = (blockIdx.x - DQ_BLOCKS) * 256 + threadIdx.x;
        float4 v0 = reinterpret_cast<const float4*>(x)[2 * idx];
        float4 v1 = reinterpret_cast<const float4*>(x)[2 * idx + 1];
        __half2 a = __floats2half2_rn(v0.x, v0.y);
        __half2 b = __floats2half2_rn(v0.z, v0.w);
        __half2 c = __floats2half2_rn(v1.x, v1.y);
        __half2 d = __floats2half2_rn(v1.z, v1.w);
        uint4 u;
        u.x = *reinterpret_cast<uint32_t*>(&a);
        u.y = *reinterpret_cast<uint32_t*>(&b);
        u.z = *reinterpret_cast<uint32_t*>(&c);
        u.w = *reinterpret_cast<uint32_t*>(&d);
        reinterpret_cast<uint4*>(g_Xh)[idx] = u;
    }
}

// ---------------------------------------------------------------------------
// TMA HMMA GEMM: 128x128 tile, BK=64, SW128 tiles, 3-stage producer/consumer
// mbarrier pipeline. 288 threads: warps 0-7 compute (R11-exact mainloop),
// warp 8 is a DEDICATED PRODUCER (issues TMA up to 3 stages ahead) — no
// compute warp ever blocks on an empty-barrier wait.
// ---------------------------------------------------------------------------
__global__ void __launch_bounds__(NTHREADS, 2)
gemm_tma(const __grid_constant__ CUtensorMap tmA,
         const __grid_constant__ CUtensorMap tmB,
         const float* __restrict__ bias, float* __restrict__ out) {
    extern __shared__ __align__(1024) char smem[];
    const uint32_t sb = smem_u32(smem);
    const uint32_t sfull  = sb + TMA_SM_BAR;        // 3 x 8B
    const uint32_t sempty = sb + TMA_SM_BAR + 24;   // 3 x 8B
    const uint32_t stile  = sb + TMA_SM_TILE;
    const int tid  = threadIdx.x;
    const int lane = tid & 31;
    const int wid  = tid >> 5;
    const int bm = blockIdx.y * BM;
    const int bn = blockIdx.x * BN;

    if (tid == 0) {
        MBARRIER_INIT(sfull + 0, 1);
        MBARRIER_INIT(sfull + 8, 1);
        MBARRIER_INIT(sfull + 16, 1);
        MBARRIER_INIT(sempty + 0, 8);       // one arrive per COMPUTE warp
        MBARRIER_INIT(sempty + 8, 8);
        MBARRIER_INIT(sempty + 16, 8);
        FENCE_ASYNC();
    }
    __syncthreads();                         // barriers visible (only CTA sync)

    if (wid == 8) {
        // ---------------- producer warp ----------------
        if (lane == 0) {
            for (int g = 0; g < NCHUNK; g++) {
                int s = g % TMA_NSTAGE;
                if (g >= TMA_NSTAGE)
                    MBAR_WAIT(sempty + s * 8, ((g - TMA_NSTAGE) / TMA_NSTAGE) & 1);
                uint32_t mb = sfull + s * 8;
                uint32_t ab = stile + s * TSTG;
                MBARRIER_EXPECT_TX(mb, 2 * 16384);
                tma2d(ab,          &tmA, g * BK, bm, mb);
                tma2d(ab + 16384,  &tmB, g * BK, bn, mb);
            }
        }
        return;
    }

    // ---------------- compute warps (0-7), R11-exact mainloop ----------------
    const int wm0 = (wid >> 2) * 64;        // warp_m 0..1
    const int wn0 = (wid & 3) * 32;         // warp_n 0..3

    // swizzled ldmatrix address components:
    // addr = tile + row*128 + ((ks*32 + seg16) ^ ((row&7)*16))
    uint32_t arow[4], arx[4], brow[2], brx[2];
    #pragma unroll
    for (int mi = 0; mi < 4; mi++) {
        int r = wm0 + mi * 16 + (lane & 15);
        arow[mi] = r * 128;
        arx[mi]  = (r & 7) * 16;
    }
    #pragma unroll
    for (int p = 0; p < 2; p++) {
        int r = wn0 + p * 16 + (lane & 15);
        brow[p] = r * 128;
        brx[p]  = (r & 7) * 16;
    }
    const uint32_t seg16 = (lane >> 4) * 16;

    float acc[4][4][4];
    #pragma unroll
    for (int i = 0; i < 4; i++)
        #pragma unroll
        for (int j = 0; j < 4; j++)
            #pragma unroll
            for (int q = 0; q < 4; q++)
                acc[i][j][q] = 0.0f;

    for (int c = 0; c < NCHUNK; c++) {
        int s = c % TMA_NSTAGE;
        MBAR_WAIT(sfull + s * 8, (c / TMA_NSTAGE) & 1);   // data resident

        uint32_t abase = stile + s * TSTG;
        uint32_t bbase = abase + 16384;

        #pragma unroll
        for (int ks = 0; ks < 4; ks++) {
            uint32_t kb = ks * 32 + seg16;
            uint32_t a[4][4], b[4][2];
            #pragma unroll
            for (int mi = 0; mi < 4; mi++)
                ldsm_x4(a[mi][0], a[mi][1], a[mi][2], a[mi][3],
                        abase + arow[mi] + (kb ^ arx[mi]));
            #pragma unroll
            for (int p = 0; p < 2; p++) {
                uint32_t r0, r1, r2, r3;
                ldsm_x4(r0, r1, r2, r3, bbase + brow[p] + (kb ^ brx[p]));
                b[p * 2 + 0][0] = r0; b[p * 2 + 0][1] = r2;
                b[p * 2 + 1][0] = r1; b[p * 2 + 1][1] = r3;
            }
            #pragma unroll
            for (int mi = 0; mi < 4; mi++)
                #pragma unroll
                for (int nj = 0; nj < 4; nj++)
                    mma_16816(acc[mi][nj], a[mi], b[nj]);
        }

        // this warp is done reading stage s
        if (lane == 0) MBARRIER_ARRIVE(sempty + s * 8);
    }

    // ---- epilogue (per-warp; each warp owns its outputs) ----
    const int row0 = lane >> 2;
    const int col0 = (lane & 3) * 2;
    #pragma unroll
    for (int mi = 0; mi < 4; mi++) {
        int m = bm + wm0 + mi * 16 + row0;
        #pragma unroll
        for (int nj = 0; nj < 4; nj++) {
            int n = bn + wn0 + nj * 8 + col0;
            float b0 = __ldg(&bias[n]);
            float b1 = __ldg(&bias[n + 1]);
            float2 v0 = make_float2(acc[mi][nj][0] + b0, acc[mi][nj][1] + b1);
            float2 v1 = make_float2(acc[mi][nj][2] + b0, acc[mi][nj][3] + b1);
            *reinterpret_cast<float2*>(&out[(size_t)m * N_DIM + n]) = v0;
            *reinterpret_cast<float2*>(&out[(size_t)(m + 8) * N_DIM + n]) = v1;
        }
    }
}

// ---------------------------------------------------------------------------
// Fallback HMMA GEMM (R4 exact: cp.async, 2-stage, 873us proven)
// ---------------------------------------------------------------------------
__global__ void __launch_bounds__(256, 2)
gemm_hmma(const float* __restrict__ bias, float* __restrict__ out) {
    extern __shared__ char smem[];
    const uint32_t sb = smem_u32(smem);
    const int tid  = threadIdx.x;
    const int lane = tid & 31;
    const int wid  = tid >> 5;
    const int wm0 = (wid >> 2) * 64;
    const int wn0 = (wid & 3) * 32;
    const int bm = blockIdx.y * BM;
    const int bn = blockIdx.x * BN;

    const char* Xbase = (const char*)(g_Xh + (size_t)bm * K_DIM);
    const char* Wbase = (const char*)(g_Wh + (size_t)bn * K_DIM);
    const int ld_row = tid >> 3;
    const int ld_seg = tid & 7;

    auto load_chunk = [&](int c, int s) {
        uint32_t abase = sb + s * FSTG;
        uint32_t bbase = abase + ASTG;
        const char* asrc = Xbase + c * (BK * 2);
        const char* bsrc = Wbase + c * (BK * 2);
        #pragma unroll
        for (int t = 0; t < 4; t++) {
            int row = ld_row + t * 32;
            uint32_t doff = row * (LDS_ROW * 2) + ld_seg * 16;
            size_t   soff = (size_t)row * (K_DIM * 2) + ld_seg * 16;
            CP_ASYNC16(abase + doff, asrc + soff);
            CP_ASYNC16(bbase + doff, bsrc + soff);
        }
        CP_COMMIT();
    };

    uint32_t aoff[4], boff[2];
    #pragma unroll
    for (int mi = 0; mi < 4; mi++)
        aoff[mi] = (wm0 + mi * 16 + (lane & 15)) * (LDS_ROW * 2) + ((lane >> 4) << 4);
    #pragma unroll
    for (int nj = 0; nj < 2; nj++)
        boff[nj] = (wn0 + nj * 16 + (lane & 15)) * (LDS_ROW * 2) + ((lane >> 4) << 4);

    float acc[4][4][4];
    #pragma unroll
    for (int i = 0; i < 4; i++)
        #pragma unroll
        for (int j = 0; j < 4; j++)
            #pragma unroll
            for (int q = 0; q < 4; q++)
                acc[i][j][q] = 0.0f;

    load_chunk(0, 0);
    for (int c = 0; c < NCHUNK; c++) {
        CP_WAIT(0);
        __syncthreads();
        if (c + 1 < NCHUNK)
            load_chunk(c + 1, (c + 1) & 1);
        uint32_t abase = sb + (c & 1) * FSTG;
        uint32_t bbase = abase + ASTG;
        #pragma unroll
        for (int ks = 0; ks < 4; ks++) {
            uint32_t koff = ks * 32;
            uint32_t a[4][4], b[4][2];
            #pragma unroll
            for (int mi = 0; mi < 4; mi++)
                ldsm_x4(a[mi][0], a[mi][1], a[mi][2], a[mi][3], abase + aoff[mi] + koff);
            #pragma unroll
            for (int njp = 0; njp < 2; njp++) {
                uint32_t r0, r1, r2, r3;
                ldsm_x4(r0, r1, r2, r3, bbase + boff[njp] + koff);
                b[njp * 2 + 0][0] = r0; b[njp * 2 + 0][1] = r2;
                b[njp * 2 + 1][0] = r1; b[njp * 2 + 1][1] = r3;
            }
            #pragma unroll
            for (int mi = 0; mi < 4; mi++)
                #pragma unroll
                for (int nj = 0; nj < 4; nj++)
                    mma_16816(acc[mi][nj], a[mi], b[nj]);
        }
    }
    const int row0 = lane >> 2;
    const int col0 = (lane & 3) * 2;
    #pragma unroll
    for (int mi = 0; mi < 4; mi++) {
        int m = bm + wm0 + mi * 16 + row0;
        #pragma unroll
        for (int nj = 0; nj < 4; nj++) {
            int n = bn + wn0 + nj * 8 + col0;
            float b0 = __ldg(&bias[n]);
            float b1 = __ldg(&bias[n + 1]);
            float2 v0 = make_float2(acc[mi][nj][0] + b0, acc[mi][nj][1] + b1);
            float2 v1 = make_float2(acc[mi][nj][2] + b0, acc[mi][nj][3] + b1);
            *reinterpret_cast<float2*>(&out[(size_t)m * N_DIM + n]) = v0;
            *reinterpret_cast<float2*>(&out[(size_t)(m + 8) * N_DIM + n]) = v1;
        }
    }
}

// ---------------------------------------------------------------------------
// Launch
// inputs: 0=x f32, 1=weight_packed i32, 2=scales f32, 3=zeros, 4=bias f32
// ---------------------------------------------------------------------------
typedef CUresult (*EncodeFn)(CUtensorMap*, CUtensorMapDataType, cuuint32_t,
                             void*, const cuuint64_t*, const cuuint64_t*,
                             const cuuint32_t*, const cuuint32_t*,
                             CUtensorMapInterleave, CUtensorMapSwizzle,
                             CUtensorMapL2promotion, CUtensorMapFloatOOBfill);

extern "C" void kernel_launch(void* const* d_in, const int* in_sizes, int n_in,
                              void* d_out, int out_size) {
    const float* x      = (const float*)d_in[0];
    const int*   wp     = (const int*)d_in[1];
    const float* scales = (const float*)d_in[2];
    const float* bias   = (const float*)d_in[4];
    float*       out    = (float*)d_out;
    (void)in_sizes; (void)n_in; (void)out_size;

    static int mode = -1;
    static CUtensorMap tmA, tmB;
    if (mode < 0) {
        mode = 0;
        EncodeFn enc = nullptr;
        cudaDriverEntryPointQueryResult qr;
        if (cudaGetDriverEntryPoint("cuTensorMapEncodeTiled", (void**)&enc,
                                    cudaEnableDefault, &qr) == cudaSuccess &&
            enc != nullptr) {
            void *pX = nullptr, *pW = nullptr;
            cudaGetSymbolAddress(&pX, g_Xh);
            cudaGetSymbolAddress(&pW, g_Wh);
            cuuint64_t dimsA[2] = {K_DIM, M_DIM};
            cuuint64_t dimsB[2] = {K_DIM, N_DIM};
            cuuint64_t strides[1] = {K_DIM * 2};
            cuuint32_t box[2] = {BK, BM};
            cuuint32_t es[2] = {1, 1};
            CUresult r1 = enc(&tmA, CU_TENSOR_MAP_DATA_TYPE_UINT16, 2, pX,
                              dimsA, strides, box, es,
                              CU_TENSOR_MAP_INTERLEAVE_NONE,
                              CU_TENSOR_MAP_SWIZZLE_128B,
                              CU_TENSOR_MAP_L2_PROMOTION_L2_128B,
                              CU_TENSOR_MAP_FLOAT_OOB_FILL_NONE);
            CUresult r2 = enc(&tmB, CU_TENSOR_MAP_DATA_TYPE_UINT16, 2, pW,
                              dimsB, strides, box, es,
                              CU_TENSOR_MAP_INTERLEAVE_NONE,
                              CU_TENSOR_MAP_SWIZZLE_128B,
                              CU_TENSOR_MAP_L2_PROMOTION_L2_128B,
                              CU_TENSOR_MAP_FLOAT_OOB_FILL_NONE);
            if (r1 == CUDA_SUCCESS && r2 == CUDA_SUCCESS) mode = 1;
        }
        cudaFuncSetAttribute(gemm_tma,
                             cudaFuncAttributeMaxDynamicSharedMemorySize,
                             TMA_SM_TOTAL);
        cudaFuncSetAttribute(gemm_hmma,
                             cudaFuncAttributeMaxDynamicSharedMemorySize,
                             FB_SM_TOTAL);
    }

    prep_kernel<<<DQ_BLOCKS + CV_BLOCKS, 256>>>(wp, scales, x);

    dim3 grid(N_DIM / BN, M_DIM / BM);   // (32, 64)
    if (mode == 1) {
        gemm_tma<<<grid, NTHREADS, TMA_SM_TOTAL>>>(tmA, tmB, bias, out);
    } else {
        gemm_hmma<<<grid, 256, FB_SM_TOTAL>>>(bias, out);
    }
}

// round 16
// speedup vs baseline: 1.6071x; 1.0253x over previous
#include <cuda_runtime.h>
#include <cuda.h>
#include <cuda_fp16.h>
#include <cstdint>

// ---------------- problem constants ----------------
#define K_DIM 4096
#define N_DIM 4096
#define M_DIM 8192            // 4 * 2048
#define GROUPS 32
#define PACKED_PER_ROW 2048   // K/2

// ---------------- GEMM tiling ----------------
#define BM 128
#define BN 128
#define BK 64                 // halves per K-chunk (=128B rows, SW128 atom)
#define NCHUNK (K_DIM / BK)   // 64
#define NTHREADS 288          // 8 compute warps + 1 producer warp

// fp16 scratch (static __device__ — no runtime allocation)
__device__ __half g_Wh[(size_t)N_DIM * K_DIM];   // 32 MB
__device__ __half g_Xh[(size_t)M_DIM * K_DIM];   // 64 MB

// ---------------- PTX helpers (baseline sm_90 features only) ----------------
__device__ __forceinline__ uint32_t smem_u32(const void* p) {
    uint32_t a;
    asm("{ .reg .u64 t; cvta.to.shared.u64 t, %1; cvt.u32.u64 %0, t; }" : "=r"(a) : "l"(p));
    return a;
}

#define CP_ASYNC16(dst, src) \
    asm volatile("cp.async.cg.shared.global [%0], [%1], 16;\n" :: "r"(dst), "l"(src))
#define CP_COMMIT()  asm volatile("cp.async.commit_group;\n" ::: "memory")
#define CP_WAIT(n)   asm volatile("cp.async.wait_group %0;\n" :: "n"(n) : "memory")

__device__ __forceinline__ void ldsm_x4(uint32_t& r0, uint32_t& r1,
                                        uint32_t& r2, uint32_t& r3, uint32_t addr) {
    asm volatile("ldmatrix.sync.aligned.m8n8.x4.shared.b16 {%0,%1,%2,%3}, [%4];"
                 : "=r"(r0), "=r"(r1), "=r"(r2), "=r"(r3) : "r"(addr));
}

__device__ __forceinline__ void mma_16816(float* d, const uint32_t* a,
                                          const uint32_t* b) {
    asm volatile(
        "mma.sync.aligned.m16n8k16.row.col.f32.f16.f16.f32 "
        "{%0,%1,%2,%3}, {%4,%5,%6,%7}, {%8,%9}, {%0,%1,%2,%3};"
        : "+f"(d[0]), "+f"(d[1]), "+f"(d[2]), "+f"(d[3])
        : "r"(a[0]), "r"(a[1]), "r"(a[2]), "r"(a[3]), "r"(b[0]), "r"(b[1]));
}

#define MBARRIER_INIT(addr, cnt) \
    asm volatile("mbarrier.init.shared.b64 [%0], %1;" :: "r"(addr), "r"(cnt) : "memory")
#define MBARRIER_EXPECT_TX(addr, bytes) \
    asm volatile("mbarrier.arrive.expect_tx.shared.b64 _, [%0], %1;" \
                 :: "r"(addr), "r"((uint32_t)(bytes)) : "memory")
#define MBARRIER_ARRIVE(addr) \
    asm volatile("mbarrier.arrive.shared.b64 _, [%0];" :: "r"(addr) : "memory")
#define FENCE_ASYNC() asm volatile("fence.proxy.async.shared::cta;" ::: "memory")

#define MBAR_WAIT(addr, parity) do {                                          \
    uint32_t _mb = (addr); uint32_t _ph = (parity); uint32_t _done;           \
    asm volatile("{\n\t.reg .pred p;\n\t"                                     \
        "mbarrier.try_wait.parity.acquire.cta.shared::cta.b64 p, [%1], %2;\n\t"\
        "selp.b32 %0, 1, 0, p;\n\t}" : "=r"(_done) : "r"(_mb), "r"(_ph) : "memory"); \
    if (!_done) {                                                             \
        asm volatile("{\n\t.reg .pred P1;\n\t"                                \
            "WL_%=:\n\t"                                                      \
            "mbarrier.try_wait.parity.acquire.cta.shared::cta.b64 P1, [%0], %1, 0x989680;\n\t" \
            "@P1 bra.uni WD_%=;\n\t"                                          \
            "bra.uni WL_%=;\n\t"                                              \
            "WD_%=:\n\t}" :: "r"(_mb), "r"(_ph) : "memory");                  \
    }                                                                         \
} while (0)

__device__ __forceinline__ void tma2d(uint32_t dst, const CUtensorMap* tm,
                                      int x, int y, uint32_t mbar) {
    asm volatile(
        "cp.async.bulk.tensor.2d.shared::cta.global.tile.mbarrier::complete_tx::bytes "
        "[%0], [%1, {%2, %3}], [%4];"
        :: "r"(dst), "l"(tm), "r"(x), "r"(y), "r"(mbar) : "memory");
}

// ---------------- TMA GEMM smem layout ----------------
#define TSTG 32768                          // A 16KB + B 16KB, SW128
#define TMA_NSTAGE 3
#define TMA_SM_BAR 0                        // 3 full + 3 empty mbarriers (48B)
#define TMA_SM_TILE 1024
#define TMA_SM_TOTAL (TMA_SM_TILE + TMA_NSTAGE * TSTG)   // 99328 -> 2 CTAs/SM

// ---------------- fallback (cp.async) layout — R4 proven ----------------
#define LDS_ROW 72
#define ASTG (BM * LDS_ROW * 2)            // 18432 B
#define FSTG (2 * ASTG)                    // 36864 B
#define FB_SM_TOTAL (2 * FSTG)             // 73728 B -> 2 CTAs/SM

// ---------------------------------------------------------------------------
// Merged prep kernel: blocks [0, DQ_BLOCKS) dequantize W; rest convert X.
// ---------------------------------------------------------------------------
#define DQ_ITEMS ((N_DIM * PACKED_PER_ROW) / 4)
#define CV_ITEMS ((M_DIM * K_DIM) / 8)
#define DQ_BLOCKS (DQ_ITEMS / 256)
#define CV_BLOCKS (CV_ITEMS / 256)

__global__ void prep_kernel(const int* __restrict__ wp,
                            const float* __restrict__ scales,
                            const float* __restrict__ x) {
    if (blockIdx.x < DQ_BLOCKS) {
        int idx = blockIdx.x * 256 + threadIdx.x;
        int4 p = reinterpret_cast<const int4*>(wp)[idx];
        int j4 = idx << 2;
        int o = j4 >> 11;
        int j = j4 & 2047;
        float s = scales[o * GROUPS + (j >> 6)];
        uint4 v;
        {
            __half2 h = __halves2half2(__float2half_rn((float)((p.x & 15) - 8) * s),
                                       __float2half_rn((float)(((p.x >> 4) & 15) - 8) * s));
            v.x = *reinterpret_cast<uint32_t*>(&h);
        }
        {
            __half2 h = __halves2half2(__float2half_rn((float)((p.y & 15) - 8) * s),
                                       __float2half_rn((float)(((p.y >> 4) & 15) - 8) * s));
            v.y = *reinterpret_cast<uint32_t*>(&h);
        }
        {
            __half2 h = __halves2half2(__float2half_rn((float)((p.z & 15) - 8) * s),
                                       __float2half_rn((float)(((p.z >> 4) & 15) - 8) * s));
            v.z = *reinterpret_cast<uint32_t*>(&h);
        }
        {
            __half2 h = __halves2half2(__float2half_rn((float)((p.w & 15) - 8) * s),
                                       __float2half_rn((float)(((p.w >> 4) & 15) - 8) * s));
            v.w = *reinterpret_cast<uint32_t*>(&h);
        }
        reinterpret_cast<uint4*>(g_Wh)[idx] = v;
    } else {
        int idx = (blockIdx.x - DQ_BLOCKS) * 256 + threadIdx.x;
        float4 v0 = reinterpret_cast<const float4*>(x)[2 * idx];
        float4 v1 = reinterpret_cast<const float4*>(x)[2 * idx + 1];
        __half2 a = __floats2half2_rn(v0.x, v0.y);
        __half2 b = __floats2half2_rn(v0.z, v0.w);
        __half2 c = __floats2half2_rn(v1.x, v1.y);
        __half2 d = __floats2half2_rn(v1.z, v1.w);
        uint4 u;
        u.x = *reinterpret_cast<uint32_t*>(&a);
        u.y = *reinterpret_cast<uint32_t*>(&b);
        u.z = *reinterpret_cast<uint32_t*>(&c);
        u.w = *reinterpret_cast<uint32_t*>(&d);
        reinterpret_cast<uint4*>(g_Xh)[idx] = u;
    }
}

// ---------------------------------------------------------------------------
// TMA HMMA GEMM: 128x128 tile, BK=64, SW128 tiles, 3-stage producer/consumer
// mbarrier pipeline. 288 threads: warps 0-7 compute, warp 8 dedicated
// producer. fence.proxy.async between empty-wait and TMA issue orders the
// consumers' generic-proxy LDSM reads before the async-proxy tile overwrite
// (this was the R14 race).
// ---------------------------------------------------------------------------
__global__ void __launch_bounds__(NTHREADS, 2)
gemm_tma(const __grid_constant__ CUtensorMap tmA,
         const __grid_constant__ CUtensorMap tmB,
         const float* __restrict__ bias, float* __restrict__ out) {
    extern __shared__ __align__(1024) char smem[];
    const uint32_t sb = smem_u32(smem);
    const uint32_t sfull  = sb + TMA_SM_BAR;        // 3 x 8B
    const uint32_t sempty = sb + TMA_SM_BAR + 24;   // 3 x 8B
    const uint32_t stile  = sb + TMA_SM_TILE;
    const int tid  = threadIdx.x;
    const int lane = tid & 31;
    const int wid  = tid >> 5;
    const int bm = blockIdx.y * BM;
    const int bn = blockIdx.x * BN;

    if (tid == 0) {
        MBARRIER_INIT(sfull + 0, 1);
        MBARRIER_INIT(sfull + 8, 1);
        MBARRIER_INIT(sfull + 16, 1);
        MBARRIER_INIT(sempty + 0, 8);       // one arrive per COMPUTE warp
        MBARRIER_INIT(sempty + 8, 8);
        MBARRIER_INIT(sempty + 16, 8);
    }
    __syncthreads();                         // barriers visible (only CTA sync)

    if (wid == 8) {
        // ---------------- producer warp ----------------
        if (lane == 0) {
            FENCE_ASYNC();   // make mbarrier inits visible to the async proxy
            for (int g = 0; g < NCHUNK; g++) {
                int s = g % TMA_NSTAGE;
                if (g >= TMA_NSTAGE) {
                    MBAR_WAIT(sempty + s * 8, ((g - TMA_NSTAGE) / TMA_NSTAGE) & 1);
                    FENCE_ASYNC();   // order consumers' generic reads before
                                     // the async-proxy tile overwrite
                }
                uint32_t mb = sfull + s * 8;
                uint32_t ab = stile + s * TSTG;
                MBARRIER_EXPECT_TX(mb, 2 * 16384);
                tma2d(ab,          &tmA, g * BK, bm, mb);
                tma2d(ab + 16384,  &tmB, g * BK, bn, mb);
            }
        }
        return;
    }

    // ---------------- compute warps (0-7), R11-exact mainloop ----------------
    const int wm0 = (wid >> 2) * 64;        // warp_m 0..1
    const int wn0 = (wid & 3) * 32;         // warp_n 0..3

    // swizzled ldmatrix address components:
    // addr = tile + row*128 + ((ks*32 + seg16) ^ ((row&7)*16))
    uint32_t arow[4], arx[4], brow[2], brx[2];
    #pragma unroll
    for (int mi = 0; mi < 4; mi++) {
        int r = wm0 + mi * 16 + (lane & 15);
        arow[mi] = r * 128;
        arx[mi]  = (r & 7) * 16;
    }
    #pragma unroll
    for (int p = 0; p < 2; p++) {
        int r = wn0 + p * 16 + (lane & 15);
        brow[p] = r * 128;
        brx[p]  = (r & 7) * 16;
    }
    const uint32_t seg16 = (lane >> 4) * 16;

    float acc[4][4][4];
    #pragma unroll
    for (int i = 0; i < 4; i++)
        #pragma unroll
        for (int j = 0; j < 4; j++)
            #pragma unroll
            for (int q = 0; q < 4; q++)
                acc[i][j][q] = 0.0f;

    for (int c = 0; c < NCHUNK; c++) {
        int s = c % TMA_NSTAGE;
        MBAR_WAIT(sfull + s * 8, (c / TMA_NSTAGE) & 1);   // data resident

        uint32_t abase = stile + s * TSTG;
        uint32_t bbase = abase + 16384;

        #pragma unroll
        for (int ks = 0; ks < 4; ks++) {
            uint32_t kb = ks * 32 + seg16;
            uint32_t a[4][4], b[4][2];
            #pragma unroll
            for (int mi = 0; mi < 4; mi++)
                ldsm_x4(a[mi][0], a[mi][1], a[mi][2], a[mi][3],
                        abase + arow[mi] + (kb ^ arx[mi]));
            #pragma unroll
            for (int p = 0; p < 2; p++) {
                uint32_t r0, r1, r2, r3;
                ldsm_x4(r0, r1, r2, r3, bbase + brow[p] + (kb ^ brx[p]));
                b[p * 2 + 0][0] = r0; b[p * 2 + 0][1] = r2;
                b[p * 2 + 1][0] = r1; b[p * 2 + 1][1] = r3;
            }
            #pragma unroll
            for (int mi = 0; mi < 4; mi++)
                #pragma unroll
                for (int nj = 0; nj < 4; nj++)
                    mma_16816(acc[mi][nj], a[mi], b[nj]);
        }

        // this warp is done reading stage s (release-arrive)
        if (lane == 0) MBARRIER_ARRIVE(sempty + s * 8);
    }

    // ---- epilogue (per-warp; each warp owns its outputs) ----
    const int row0 = lane >> 2;
    const int col0 = (lane & 3) * 2;
    #pragma unroll
    for (int mi = 0; mi < 4; mi++) {
        int m = bm + wm0 + mi * 16 + row0;
        #pragma unroll
        for (int nj = 0; nj < 4; nj++) {
            int n = bn + wn0 + nj * 8 + col0;
            float b0 = __ldg(&bias[n]);
            float b1 = __ldg(&bias[n + 1]);
            float2 v0 = make_float2(acc[mi][nj][0] + b0, acc[mi][nj][1] + b1);
            float2 v1 = make_float2(acc[mi][nj][2] + b0, acc[mi][nj][3] + b1);
            *reinterpret_cast<float2*>(&out[(size_t)m * N_DIM + n]) = v0;
            *reinterpret_cast<float2*>(&out[(size_t)(m + 8) * N_DIM + n]) = v1;
        }
    }
}

// ---------------------------------------------------------------------------
// Fallback HMMA GEMM (R4 exact: cp.async, 2-stage, 873us proven)
// ---------------------------------------------------------------------------
__global__ void __launch_bounds__(256, 2)
gemm_hmma(const float* __restrict__ bias, float* __restrict__ out) {
    extern __shared__ char smem[];
    const uint32_t sb = smem_u32(smem);
    const int tid  = threadIdx.x;
    const int lane = tid & 31;
    const int wid  = tid >> 5;
    const int wm0 = (wid >> 2) * 64;
    const int wn0 = (wid & 3) * 32;
    const int bm = blockIdx.y * BM;
    const int bn = blockIdx.x * BN;

    const char* Xbase = (const char*)(g_Xh + (size_t)bm * K_DIM);
    const char* Wbase = (const char*)(g_Wh + (size_t)bn * K_DIM);
    const int ld_row = tid >> 3;
    const int ld_seg = tid & 7;

    auto load_chunk = [&](int c, int s) {
        uint32_t abase = sb + s * FSTG;
        uint32_t bbase = abase + ASTG;
        const char* asrc = Xbase + c * (BK * 2);
        const char* bsrc = Wbase + c * (BK * 2);
        #pragma unroll
        for (int t = 0; t < 4; t++) {
            int row = ld_row + t * 32;
            uint32_t doff = row * (LDS_ROW * 2) + ld_seg * 16;
            size_t   soff = (size_t)row * (K_DIM * 2) + ld_seg * 16;
            CP_ASYNC16(abase + doff, asrc + soff);
            CP_ASYNC16(bbase + doff, bsrc + soff);
        }
        CP_COMMIT();
    };

    uint32_t aoff[4], boff[2];
    #pragma unroll
    for (int mi = 0; mi < 4; mi++)
        aoff[mi] = (wm0 + mi * 16 + (lane & 15)) * (LDS_ROW * 2) + ((lane >> 4) << 4);
    #pragma unroll
    for (int nj = 0; nj < 2; nj++)
        boff[nj] = (wn0 + nj * 16 + (lane & 15)) * (LDS_ROW * 2) + ((lane >> 4) << 4);

    float acc[4][4][4];
    #pragma unroll
    for (int i = 0; i < 4; i++)
        #pragma unroll
        for (int j = 0; j < 4; j++)
            #pragma unroll
            for (int q = 0; q < 4; q++)
                acc[i][j][q] = 0.0f;

    load_chunk(0, 0);
    for (int c = 0; c < NCHUNK; c++) {
        CP_WAIT(0);
        __syncthreads();
        if (c + 1 < NCHUNK)
            load_chunk(c + 1, (c + 1) & 1);
        uint32_t abase = sb + (c & 1) * FSTG;
        uint32_t bbase = abase + ASTG;
        #pragma unroll
        for (int ks = 0; ks < 4; ks++) {
            uint32_t koff = ks * 32;
            uint32_t a[4][4], b[4][2];
            #pragma unroll
            for (int mi = 0; mi < 4; mi++)
                ldsm_x4(a[mi][0], a[mi][1], a[mi][2], a[mi][3], abase + aoff[mi] + koff);
            #pragma unroll
            for (int njp = 0; njp < 2; njp++) {
                uint32_t r0, r1, r2, r3;
                ldsm_x4(r0, r1, r2, r3, bbase + boff[njp] + koff);
                b[njp * 2 + 0][0] = r0; b[njp * 2 + 0][1] = r2;
                b[njp * 2 + 1][0] = r1; b[njp * 2 + 1][1] = r3;
            }
            #pragma unroll
            for (int mi = 0; mi < 4; mi++)
                #pragma unroll
                for (int nj = 0; nj < 4; nj++)
                    mma_16816(acc[mi][nj], a[mi], b[nj]);
        }
    }
    const int row0 = lane >> 2;
    const int col0 = (lane & 3) * 2;
    #pragma unroll
    for (int mi = 0; mi < 4; mi++) {
        int m = bm + wm0 + mi * 16 + row0;
        #pragma unroll
        for (int nj = 0; nj < 4; nj++) {
            int n = bn + wn0 + nj * 8 + col0;
            float b0 = __ldg(&bias[n]);
            float b1 = __ldg(&bias[n + 1]);
            float2 v0 = make_float2(acc[mi][nj][0] + b0, acc[mi][nj][1] + b1);
            float2 v1 = make_float2(acc[mi][nj][2] + b0, acc[mi][nj][3] + b1);
            *reinterpret_cast<float2*>(&out[(size_t)m * N_DIM + n]) = v0;
            *reinterpret_cast<float2*>(&out[(size_t)(m + 8) * N_DIM + n]) = v1;
        }
    }
}

// ---------------------------------------------------------------------------
// Launch
// inputs: 0=x f32, 1=weight_packed i32, 2=scales f32, 3=zeros, 4=bias f32
// ---------------------------------------------------------------------------
typedef CUresult (*EncodeFn)(CUtensorMap*, CUtensorMapDataType, cuuint32_t,
                             void*, const cuuint64_t*, const cuuint64_t*,
                             const cuuint32_t*, const cuuint32_t*,
                             CUtensorMapInterleave, CUtensorMapSwizzle,
                             CUtensorMapL2promotion, CUtensorMapFloatOOBfill);

extern "C" void kernel_launch(void* const* d_in, const int* in_sizes, int n_in,
                              void* d_out, int out_size) {
    const float* x      = (const float*)d_in[0];
    const int*   wp     = (const int*)d_in[1];
    const float* scales = (const float*)d_in[2];
    const float* bias   = (const float*)d_in[4];
    float*       out    = (float*)d_out;
    (void)in_sizes; (void)n_in; (void)out_size;

    static int mode = -1;
    static CUtensorMap tmA, tmB;
    if (mode < 0) {
        mode = 0;
        EncodeFn enc = nullptr;
        cudaDriverEntryPointQueryResult qr;
        if (cudaGetDriverEntryPoint("cuTensorMapEncodeTiled", (void**)&enc,
                                    cudaEnableDefault, &qr) == cudaSuccess &&
            enc != nullptr) {
            void *pX = nullptr, *pW = nullptr;
            cudaGetSymbolAddress(&pX, g_Xh);
            cudaGetSymbolAddress(&pW, g_Wh);
            cuuint64_t dimsA[2] = {K_DIM, M_DIM};
            cuuint64_t dimsB[2] = {K_DIM, N_DIM};
            cuuint64_t strides[1] = {K_DIM * 2};
            cuuint32_t box[2] = {BK, BM};
            cuuint32_t es[2] = {1, 1};
            CUresult r1 = enc(&tmA, CU_TENSOR_MAP_DATA_TYPE_UINT16, 2, pX,
                              dimsA, strides, box, es,
                              CU_TENSOR_MAP_INTERLEAVE_NONE,
                              CU_TENSOR_MAP_SWIZZLE_128B,
                              CU_TENSOR_MAP_L2_PROMOTION_L2_128B,
                              CU_TENSOR_MAP_FLOAT_OOB_FILL_NONE);
            CUresult r2 = enc(&tmB, CU_TENSOR_MAP_DATA_TYPE_UINT16, 2, pW,
                              dimsB, strides, box, es,
                              CU_TENSOR_MAP_INTERLEAVE_NONE,
                              CU_TENSOR_MAP_SWIZZLE_128B,
                              CU_TENSOR_MAP_L2_PROMOTION_L2_128B,
                              CU_TENSOR_MAP_FLOAT_OOB_FILL_NONE);
            if (r1 == CUDA_SUCCESS && r2 == CUDA_SUCCESS) mode = 1;
        }
        cudaFuncSetAttribute(gemm_tma,
                             cudaFuncAttributeMaxDynamicSharedMemorySize,
                             TMA_SM_TOTAL);
        cudaFuncSetAttribute(gemm_hmma,
                             cudaFuncAttributeMaxDynamicSharedMemorySize,
                             FB_SM_TOTAL);
    }

    prep_kernel<<<DQ_BLOCKS + CV_BLOCKS, 256>>>(wp, scales, x);

    dim3 grid(N_DIM / BN, M_DIM / BM);   // (32, 64)
    if (mode == 1) {
        gemm_tma<<<grid, NTHREADS, TMA_SM_TOTAL>>>(tmA, tmB, bias, out);
    } else {
        gemm_hmma<<<grid, 256, FB_SM_TOTAL>>>(bias, out);
    }
}